// round 13
// baseline (speedup 1.0000x reference)
#include <cuda_runtime.h>
#include <cuda_fp16.h>
#include <math.h>
#include <stdint.h>

#define N_NODES 50000
#define N_EDGES 800000
#define H 256

// ================= scratch (static device globals) =================
__device__ int   g_is64;
__device__ int   g_deg[N_NODES];
__device__ int   g_pre[N_NODES];
__device__ int   g_rowptr[N_NODES + 1];
__device__ int   g_cursor[N_NODES];
__device__ int   g_bsum[256];
__device__ int   g_binc[256];
__device__ int   g_col[N_EDGES];

__device__ __half g_f0[(size_t)N_NODES * H];
__device__ __half g_f1[(size_t)N_NODES * H];
__device__ __half g_y [(size_t)N_NODES * H];
__device__ float  g_yr[(size_t)N_NODES * H];
__device__ __half g_bw[3 * 512 * H];

// ================= helpers =================
__device__ __forceinline__ uint32_t smem_u32(const void* p) {
    uint32_t a;
    asm("{ .reg .u64 t; cvta.to.shared.u64 t, %1; cvt.u32.u64 %0, t; }" : "=r"(a) : "l"(p));
    return a;
}
#define LDSM_X4(r0, r1, r2, r3, addr) \
    asm volatile("ldmatrix.sync.aligned.m8n8.x4.shared.b16 {%0,%1,%2,%3}, [%4];" \
        : "=r"(r0), "=r"(r1), "=r"(r2), "=r"(r3) : "r"(addr))
#define MMA_FP16(d, a, b0, b1) \
    asm volatile("mma.sync.aligned.m16n8k16.row.col.f32.f16.f16.f32 " \
        "{%0,%1,%2,%3}, {%4,%5,%6,%7}, {%8,%9}, {%0,%1,%2,%3};" \
        : "+f"((d)[0]), "+f"((d)[1]), "+f"((d)[2]), "+f"((d)[3]) \
        : "r"((a)[0]), "r"((a)[1]), "r"((a)[2]), "r"((a)[3]), "r"(b0), "r"(b1))
#define CP_ASYNC16(saddr, gptr, sz) \
    asm volatile("cp.async.cg.shared.global [%0], [%1], 16, %2;" :: "r"(saddr), "l"(gptr), "r"(sz))
#define CP_COMMIT() asm volatile("cp.async.commit_group;" ::: "memory")
#define CP_WAIT2()  asm volatile("cp.async.wait_group 2;" ::: "memory")

// ================= edge dtype detection =================
__global__ void detect_kernel(const int* ei) {
    if (threadIdx.x == 0 && blockIdx.x == 0) {
        int is64 = 1;
        for (int i = 1; i < 64; i += 2)
            if (ei[i] != 0) { is64 = 0; break; }
        g_is64 = is64;
    }
}
__device__ __forceinline__ int edge_val(const void* ei, int idx) {
    if (g_is64) return (int)((const long long*)ei)[idx];
    return ((const int*)ei)[idx];
}

// ================= CSR build =================
__global__ void zero_deg_kernel() {
    int i = blockIdx.x * blockDim.x + threadIdx.x;
    if (i < N_NODES) g_deg[i] = 0;
}
__global__ void hist_kernel(const void* ei) {
    int e = blockIdx.x * blockDim.x + threadIdx.x;
    if (e < N_EDGES) atomicAdd(&g_deg[edge_val(ei, N_EDGES + e)], 1);
}
__global__ void scan1_kernel() {
    __shared__ int sh[256];
    int t = threadIdx.x, i = blockIdx.x * 256 + t;
    int v = (i < N_NODES) ? g_deg[i] : 0;
    sh[t] = v; __syncthreads();
    #pragma unroll
    for (int off = 1; off < 256; off <<= 1) {
        int x = sh[t]; int add = (t >= off) ? sh[t - off] : 0;
        __syncthreads(); sh[t] = x + add; __syncthreads();
    }
    if (i < N_NODES) g_pre[i] = sh[t];
    if (t == 255) g_bsum[blockIdx.x] = sh[255];
}
__global__ void scan2_kernel(int nblocks) {
    __shared__ int sh[256];
    int t = threadIdx.x;
    sh[t] = (t < nblocks) ? g_bsum[t] : 0; __syncthreads();
    #pragma unroll
    for (int off = 1; off < 256; off <<= 1) {
        int x = sh[t]; int add = (t >= off) ? sh[t - off] : 0;
        __syncthreads(); sh[t] = x + add; __syncthreads();
    }
    g_binc[t] = sh[t];
}
__global__ void scan3_kernel(int nblocks) {
    int t = threadIdx.x, b = blockIdx.x, i = b * 256 + t;
    if (i < N_NODES) {
        int boff = (b > 0) ? g_binc[b - 1] : 0;
        int r = boff + g_pre[i] - g_deg[i];
        g_rowptr[i] = r;
        g_cursor[i] = r;
    }
    if (i == 0) g_rowptr[N_NODES] = g_binc[nblocks - 1];
}
__global__ void fill_kernel(const void* ei) {
    int e = blockIdx.x * blockDim.x + threadIdx.x;
    if (e < N_EDGES) {
        int s = edge_val(ei, e);
        int d = edge_val(ei, N_EDGES + e);
        g_col[atomicAdd(&g_cursor[d], 1)] = s;
    }
}

// ================= one-time operand conversions =================
__global__ void conv_x_kernel(const float* __restrict__ x) {
    int t = blockIdx.x * blockDim.x + threadIdx.x;
    if (t >= N_NODES * H / 4) return;
    float4 v = *(const float4*)(x + (size_t)t * 4);
    *(__half2*)(g_f0 + (size_t)t * 4)     = __float22half2_rn(make_float2(v.x, v.y));
    *(__half2*)(g_f0 + (size_t)t * 4 + 2) = __float22half2_rn(make_float2(v.z, v.w));
}
__global__ void conv_w_kernel(const float* Wl1, const float* Wr1,
                              const float* Wl2, const float* Wr2,
                              const float* Wl3, const float* Wr3) {
    int t = blockIdx.x * blockDim.x + threadIdx.x;
    const int PER_L = 512 * H / 4;
    if (t >= 3 * PER_L) return;
    int l = t / PER_L, r = t % PER_L;
    int j = r >> 6, q = r & 63;
    const float* Wl = (l == 0) ? Wl1 : (l == 1) ? Wl2 : Wl3;
    const float* Wr = (l == 0) ? Wr1 : (l == 1) ? Wr2 : Wr3;
    const float* src = (j < 256) ? (Wl + (size_t)j * H) : (Wr + (size_t)(j - 256) * H);
    float4 v = *(const float4*)(src + q * 4);
    size_t o = (size_t)l * 512 * H + (size_t)j * H + q * 4;
    *(__half2*)(g_bw + o)     = __float22half2_rn(make_float2(v.x, v.y));
    *(__half2*)(g_bw + o + 2) = __float22half2_rn(make_float2(v.z, v.w));
}

// ================= GEMM: y = h @ [Wl;Wr]^T  (K=256, N=512), plain fp16 =================
// BM=128; each CTA does TWO column passes: bn = by*128 (y_l) then by*128+256 (y_r).
// A is smem-RESIDENT (written once, full K), B rings through 4 stages.
// 8 warps (4m x 2n), warp tile 32x64; 3 chunks in flight; 16 pipeline steps.
#define ASTRIDE_A 528               // 256 halfs * 2B + 16B pad (odd multiple of 16B)
#define ASTRIDE_B 80
#define A_BYTES   (128 * 528)       // 67584
#define B_STAGE   10240
#define NSTAGE    4
#define GEMM_SMEM (A_BYTES + NSTAGE * B_STAGE)   // 108544

__global__ __launch_bounds__(256, 2) void gemm_mma_kernel(int in_sel, int layer)
{
    extern __shared__ char smem[];
    const __half* A  = in_sel ? g_f1 : g_f0;
    const __half* Bw = g_bw + (size_t)layer * 512 * H;
    uint32_t sbase = smem_u32(smem);
    uint32_t bbase = sbase + A_BYTES;

    int tid = threadIdx.x;
    int lane = tid & 31, wid = tid >> 5;
    int warp_m = wid & 3, warp_n = wid >> 2;
    int bm = blockIdx.x * 128;
    int by = blockIdx.y;                 // 0 or 1
    int wm = warp_m * 32, wn = warp_n * 64;

    // A loads: rows tid>>2 and +64, quad (tid&3)
    int am0 = tid >> 2, aq = (tid & 3) * 8;
    int am1 = am0 + 64;
    // B loads: row tid>>1 (0..127), quads (tid&1)*2, +1
    int brow = tid >> 1, bq = (tid & 1) * 2;
    int gm0 = bm + am0, gm1 = bm + am1;
    int v0 = (gm0 < N_NODES) ? 16 : 0;
    int v1 = (gm1 < N_NODES) ? 16 : 0;
    int c0 = (gm0 < N_NODES) ? gm0 : N_NODES - 1;
    int c1 = (gm1 < N_NODES) ? gm1 : N_NODES - 1;

    // logical step t in [0,16): pass = t>>3, kchunk = t&7.
    // pass 0: A chunk -> persistent region + B(bn_lo); pass 1: B(bn_hi) only.
    auto issue = [&](int t) {
        int c = t & 7;
        int kk = c * 32;
        if (t < 8) {
            uint32_t sa0 = sbase + am0 * ASTRIDE_A + c * 64 + (tid & 3) * 16;
            uint32_t sa1 = sbase + am1 * ASTRIDE_A + c * 64 + (tid & 3) * 16;
            CP_ASYNC16(sa0, A + (size_t)c0 * H + kk + aq, v0);
            CP_ASYNC16(sa1, A + (size_t)c1 * H + kk + aq, v1);
        }
        int bn = by * 128 + ((t < 8) ? 0 : 256);
        uint32_t sbb = bbase + (t & 3) * B_STAGE + brow * ASTRIDE_B + bq * 16;
        const __half* bg = Bw + (size_t)(bn + brow) * H + kk + bq * 8;
        CP_ASYNC16(sbb,      bg,     16);
        CP_ASYNC16(sbb + 16, bg + 8, 16);
    };

    float acc[2][8][4];
    #pragma unroll
    for (int a = 0; a < 2; a++)
        #pragma unroll
        for (int b = 0; b < 8; b++)
            #pragma unroll
            for (int cc = 0; cc < 4; cc++) acc[a][b][cc] = 0.f;

    issue(0); CP_COMMIT();
    issue(1); CP_COMMIT();
    issue(2); CP_COMMIT();

    for (int t = 0; t < 16; t++) {
        CP_WAIT2();              // step t's copies retired
        __syncthreads();         // visible to all; stage (t-1)%4 reads done

        if (t + 3 < 16) issue(t + 3);
        CP_COMMIT();

        int c = t & 7;
        uint32_t bstg = bbase + (t & 3) * B_STAGE;
        #pragma unroll
        for (int ks = 0; ks < 2; ks++) {
            uint32_t am[2][4], bh[4][4];
            #pragma unroll
            for (int mt = 0; mt < 2; mt++) {
                int row = wm + mt * 16 + (lane & 15);
                int kk = c * 32 + ks * 16 + (lane >> 4) * 8;
                LDSM_X4(am[mt][0], am[mt][1], am[mt][2], am[mt][3],
                        sbase + row * ASTRIDE_A + kk * 2);
            }
            #pragma unroll
            for (int p = 0; p < 4; p++) {
                int n = wn + p * 16 + (lane >> 4) * 8 + (lane & 7);
                int kk = ks * 16 + ((lane >> 3) & 1) * 8;
                LDSM_X4(bh[p][0], bh[p][1], bh[p][2], bh[p][3],
                        bstg + n * ASTRIDE_B + kk * 2);
            }
            #pragma unroll
            for (int mt = 0; mt < 2; mt++) {
                #pragma unroll
                for (int nt = 0; nt < 8; nt++) {
                    MMA_FP16(acc[mt][nt], am[mt],
                             bh[nt >> 1][(nt & 1) * 2], bh[nt >> 1][(nt & 1) * 2 + 1]);
                }
            }
        }

        if (t == 7) {
            // pass-1 epilogue: y_l fp16, cols by*128 + [0,128)
            #pragma unroll
            for (int mt = 0; mt < 2; mt++) {
                #pragma unroll
                for (int nt = 0; nt < 8; nt++) {
                    int row0 = bm + wm + mt * 16 + (lane >> 2);
                    int row1 = row0 + 8;
                    int col  = by * 128 + wn + nt * 8 + (lane & 3) * 2;
                    if (row0 < N_NODES)
                        *(__half2*)(g_y + (size_t)row0 * H + col) =
                            __float22half2_rn(make_float2(acc[mt][nt][0], acc[mt][nt][1]));
                    if (row1 < N_NODES)
                        *(__half2*)(g_y + (size_t)row1 * H + col) =
                            __float22half2_rn(make_float2(acc[mt][nt][2], acc[mt][nt][3]));
                    #pragma unroll
                    for (int cc = 0; cc < 4; cc++) acc[mt][nt][cc] = 0.f;
                }
            }
        }
    }

    // pass-2 epilogue: y_r fp32, cols (within y_r block) by*128 + [0,128)
    #pragma unroll
    for (int mt = 0; mt < 2; mt++) {
        #pragma unroll
        for (int nt = 0; nt < 8; nt++) {
            int row0 = bm + wm + mt * 16 + (lane >> 2);
            int row1 = row0 + 8;
            int cr   = by * 128 + wn + nt * 8 + (lane & 3) * 2;
            if (row0 < N_NODES)
                *(float2*)(g_yr + (size_t)row0 * H + cr) = make_float2(acc[mt][nt][0], acc[mt][nt][1]);
            if (row1 < N_NODES)
                *(float2*)(g_yr + (size_t)row1 * H + cr) = make_float2(acc[mt][nt][2], acc[mt][nt][3]);
        }
    }
}

// ================= combine: mean(y_l) + y_r + bias -> ELU =================
__global__ __launch_bounds__(256) void combine_kernel(
    const float* __restrict__ bias, int out_sel /*0->f0, 1->f1, 2->fp32 out*/,
    float* __restrict__ out_f32)
{
    int node = blockIdx.x * 8 + (threadIdx.x >> 5);
    int lane = threadIdx.x & 31;
    if (node >= N_NODES) return;
    int beg = g_rowptr[node], end = g_rowptr[node + 1];

    float acc[8];
    #pragma unroll
    for (int i = 0; i < 8; i++) acc[i] = 0.f;

    int j = beg;
    for (; j + 2 <= end; j += 2) {
        int s0 = g_col[j], s1 = g_col[j + 1];
        uint4 u0 = __ldg((const uint4*)(g_y + (size_t)s0 * H) + lane);
        uint4 u1 = __ldg((const uint4*)(g_y + (size_t)s1 * H) + lane);
        const __half2* h0 = (const __half2*)&u0;
        const __half2* h1 = (const __half2*)&u1;
        #pragma unroll
        for (int p = 0; p < 4; p++) {
            float2 f0 = __half22float2(h0[p]);
            float2 f1 = __half22float2(h1[p]);
            acc[p * 2 + 0] += f0.x + f1.x;
            acc[p * 2 + 1] += f0.y + f1.y;
        }
    }
    if (j < end) {
        uint4 u0 = __ldg((const uint4*)(g_y + (size_t)g_col[j] * H) + lane);
        const __half2* h0 = (const __half2*)&u0;
        #pragma unroll
        for (int p = 0; p < 4; p++) {
            float2 f0 = __half22float2(h0[p]);
            acc[p * 2 + 0] += f0.x;
            acc[p * 2 + 1] += f0.y;
        }
    }
    float inv = 1.0f / fmaxf((float)(end - beg), 1.0f);

    size_t rbase = (size_t)node * H + lane * 8;
    float4 r0 = __ldg((const float4*)(g_yr + rbase));
    float4 r1 = __ldg((const float4*)(g_yr + rbase + 4));
    float rr[8] = {r0.x, r0.y, r0.z, r0.w, r1.x, r1.y, r1.z, r1.w};
    float4 b0 = __ldg((const float4*)(bias + lane * 8));
    float4 b1 = __ldg((const float4*)(bias + lane * 8 + 4));
    float bb[8] = {b0.x, b0.y, b0.z, b0.w, b1.x, b1.y, b1.z, b1.w};

    float o[8];
    #pragma unroll
    for (int i = 0; i < 8; i++) {
        o[i] = acc[i] * inv + rr[i] + bb[i];
        o[i] = (o[i] > 0.f) ? o[i] : expm1f(o[i]);
    }

    size_t base = (size_t)node * H + lane * 8;
    if (out_sel == 2) {
        *(float4*)(out_f32 + base)     = make_float4(o[0], o[1], o[2], o[3]);
        *(float4*)(out_f32 + base + 4) = make_float4(o[4], o[5], o[6], o[7]);
    } else {
        __half* O = out_sel ? g_f1 : g_f0;
        *(__half2*)(O + base)     = __float22half2_rn(make_float2(o[0], o[1]));
        *(__half2*)(O + base + 2) = __float22half2_rn(make_float2(o[2], o[3]));
        *(__half2*)(O + base + 4) = __float22half2_rn(make_float2(o[4], o[5]));
        *(__half2*)(O + base + 6) = __float22half2_rn(make_float2(o[6], o[7]));
    }
}

// ================= launch =================
extern "C" void kernel_launch(void* const* d_in, const int* in_sizes, int n_in,
                              void* d_out, int out_size) {
    const float* x   = (const float*)d_in[0];
    const void*  ei  = d_in[1];
    const float* Wl1 = (const float*)d_in[2];
    const float* Wr1 = (const float*)d_in[3];
    const float* Wl2 = (const float*)d_in[4];
    const float* Wr2 = (const float*)d_in[5];
    const float* Wl3 = (const float*)d_in[6];
    const float* Wr3 = (const float*)d_in[7];
    const float* bl1 = (const float*)d_in[8];
    const float* bl2 = (const float*)d_in[9];
    const float* bl3 = (const float*)d_in[10];
    float* out = (float*)d_out;

    cudaFuncSetAttribute(gemm_mma_kernel, cudaFuncAttributeMaxDynamicSharedMemorySize, GEMM_SMEM);

    const int SCAN_BLKS = (N_NODES + 255) / 256;
    dim3 ggrid((N_NODES + 127) / 128, 2);          // 391 x 2, two col-passes per CTA
    int cblocks = (N_NODES + 7) / 8;

    cudaStream_t s1;
    cudaStreamCreateWithFlags(&s1, cudaStreamNonBlocking);
    cudaEvent_t eFork, eJoin;
    cudaEventCreateWithFlags(&eFork, cudaEventDisableTiming);
    cudaEventCreateWithFlags(&eJoin, cudaEventDisableTiming);

    // main branch first so gemm1 is the 4th launch (ncu samples #4)
    detect_kernel<<<1, 32>>>((const int*)ei);
    cudaEventRecord(eFork, 0);
    conv_x_kernel<<<(N_NODES * H / 4 + 255) / 256, 256>>>(x);
    conv_w_kernel<<<(3 * 512 * H / 4 + 255) / 256, 256>>>(Wl1, Wr1, Wl2, Wr2, Wl3, Wr3);
    gemm_mma_kernel<<<ggrid, 256, GEMM_SMEM>>>(0, 0);     // layer-1 GEMM (profiled)

    // side branch: CSR build (waits on detect), overlaps conv+gemm1
    cudaStreamWaitEvent(s1, eFork, 0);
    zero_deg_kernel<<<SCAN_BLKS, 256, 0, s1>>>();
    hist_kernel<<<(N_EDGES + 255) / 256, 256, 0, s1>>>(ei);
    scan1_kernel<<<SCAN_BLKS, 256, 0, s1>>>();
    scan2_kernel<<<1, 256, 0, s1>>>(SCAN_BLKS);
    scan3_kernel<<<SCAN_BLKS, 256, 0, s1>>>(SCAN_BLKS);
    fill_kernel<<<(N_EDGES + 255) / 256, 256, 0, s1>>>(ei);
    cudaEventRecord(eJoin, s1);

    cudaStreamWaitEvent(0, eJoin, 0);                     // combine needs CSR

    combine_kernel<<<cblocks, 256>>>(bl1, 1, out);        // layer 1 -> f1
    gemm_mma_kernel<<<ggrid, 256, GEMM_SMEM>>>(1, 1);     // layer 2
    combine_kernel<<<cblocks, 256>>>(bl2, 0, out);        //        -> f0
    gemm_mma_kernel<<<ggrid, 256, GEMM_SMEM>>>(0, 2);     // layer 3
    combine_kernel<<<cblocks, 256>>>(bl3, 2, out);        //        -> d_out
}

// round 14
// speedup vs baseline: 1.0501x; 1.0501x over previous
#include <cuda_runtime.h>
#include <cuda_fp16.h>
#include <math.h>
#include <stdint.h>

#define N_NODES 50000
#define N_EDGES 800000
#define H 256

// ================= scratch (static device globals) =================
__device__ int   g_is64;
__device__ int   g_deg[N_NODES];
__device__ int   g_pre[N_NODES];
__device__ int   g_rowptr[N_NODES + 1];
__device__ int   g_cursor[N_NODES];
__device__ int   g_bsum[256];
__device__ int   g_binc[256];
__device__ int   g_col[N_EDGES];

__device__ __half g_f0[(size_t)N_NODES * H];
__device__ __half g_f1[(size_t)N_NODES * H];
__device__ __half g_y [(size_t)N_NODES * H];   // y_l (gathered) fp16
__device__ __half g_yr[(size_t)N_NODES * H];   // y_r (self)     fp16
__device__ __half g_bw[3 * 512 * H];

// ================= helpers =================
__device__ __forceinline__ uint32_t smem_u32(const void* p) {
    uint32_t a;
    asm("{ .reg .u64 t; cvta.to.shared.u64 t, %1; cvt.u32.u64 %0, t; }" : "=r"(a) : "l"(p));
    return a;
}
#define LDSM_X4(r0, r1, r2, r3, addr) \
    asm volatile("ldmatrix.sync.aligned.m8n8.x4.shared.b16 {%0,%1,%2,%3}, [%4];" \
        : "=r"(r0), "=r"(r1), "=r"(r2), "=r"(r3) : "r"(addr))
#define MMA_FP16(d, a, b0, b1) \
    asm volatile("mma.sync.aligned.m16n8k16.row.col.f32.f16.f16.f32 " \
        "{%0,%1,%2,%3}, {%4,%5,%6,%7}, {%8,%9}, {%0,%1,%2,%3};" \
        : "+f"((d)[0]), "+f"((d)[1]), "+f"((d)[2]), "+f"((d)[3]) \
        : "r"((a)[0]), "r"((a)[1]), "r"((a)[2]), "r"((a)[3]), "r"(b0), "r"(b1))
#define CP_ASYNC16(saddr, gptr, sz) \
    asm volatile("cp.async.cg.shared.global [%0], [%1], 16, %2;" :: "r"(saddr), "l"(gptr), "r"(sz))
#define CP_COMMIT() asm volatile("cp.async.commit_group;" ::: "memory")
#define CP_WAIT2()  asm volatile("cp.async.wait_group 2;" ::: "memory")

// ================= edge dtype detection =================
__global__ void detect_kernel(const int* ei) {
    if (threadIdx.x == 0 && blockIdx.x == 0) {
        int is64 = 1;
        for (int i = 1; i < 64; i += 2)
            if (ei[i] != 0) { is64 = 0; break; }
        g_is64 = is64;
    }
}
__device__ __forceinline__ int edge_val(const void* ei, int idx) {
    if (g_is64) return (int)((const long long*)ei)[idx];
    return ((const int*)ei)[idx];
}

// ================= CSR build =================
__global__ void zero_deg_kernel() {
    int i = blockIdx.x * blockDim.x + threadIdx.x;
    if (i < N_NODES) g_deg[i] = 0;
}
__global__ void hist_kernel(const void* ei) {
    int e = blockIdx.x * blockDim.x + threadIdx.x;
    if (e < N_EDGES) atomicAdd(&g_deg[edge_val(ei, N_EDGES + e)], 1);
}
__global__ void scan1_kernel() {
    __shared__ int sh[256];
    int t = threadIdx.x, i = blockIdx.x * 256 + t;
    int v = (i < N_NODES) ? g_deg[i] : 0;
    sh[t] = v; __syncthreads();
    #pragma unroll
    for (int off = 1; off < 256; off <<= 1) {
        int x = sh[t]; int add = (t >= off) ? sh[t - off] : 0;
        __syncthreads(); sh[t] = x + add; __syncthreads();
    }
    if (i < N_NODES) g_pre[i] = sh[t];
    if (t == 255) g_bsum[blockIdx.x] = sh[255];
}
__global__ void scan2_kernel(int nblocks) {
    __shared__ int sh[256];
    int t = threadIdx.x;
    sh[t] = (t < nblocks) ? g_bsum[t] : 0; __syncthreads();
    #pragma unroll
    for (int off = 1; off < 256; off <<= 1) {
        int x = sh[t]; int add = (t >= off) ? sh[t - off] : 0;
        __syncthreads(); sh[t] = x + add; __syncthreads();
    }
    g_binc[t] = sh[t];
}
__global__ void scan3_kernel(int nblocks) {
    int t = threadIdx.x, b = blockIdx.x, i = b * 256 + t;
    if (i < N_NODES) {
        int boff = (b > 0) ? g_binc[b - 1] : 0;
        int r = boff + g_pre[i] - g_deg[i];
        g_rowptr[i] = r;
        g_cursor[i] = r;
    }
    if (i == 0) g_rowptr[N_NODES] = g_binc[nblocks - 1];
}
__global__ void fill_kernel(const void* ei) {
    int e = blockIdx.x * blockDim.x + threadIdx.x;
    if (e < N_EDGES) {
        int s = edge_val(ei, e);
        int d = edge_val(ei, N_EDGES + e);
        g_col[atomicAdd(&g_cursor[d], 1)] = s;
    }
}

// ================= one-time operand conversions =================
__global__ void conv_x_kernel(const float* __restrict__ x) {
    int t = blockIdx.x * blockDim.x + threadIdx.x;
    if (t >= N_NODES * H / 4) return;
    float4 v = *(const float4*)(x + (size_t)t * 4);
    *(__half2*)(g_f0 + (size_t)t * 4)     = __float22half2_rn(make_float2(v.x, v.y));
    *(__half2*)(g_f0 + (size_t)t * 4 + 2) = __float22half2_rn(make_float2(v.z, v.w));
}
__global__ void conv_w_kernel(const float* Wl1, const float* Wr1,
                              const float* Wl2, const float* Wr2,
                              const float* Wl3, const float* Wr3) {
    int t = blockIdx.x * blockDim.x + threadIdx.x;
    const int PER_L = 512 * H / 4;
    if (t >= 3 * PER_L) return;
    int l = t / PER_L, r = t % PER_L;
    int j = r >> 6, q = r & 63;
    const float* Wl = (l == 0) ? Wl1 : (l == 1) ? Wl2 : Wl3;
    const float* Wr = (l == 0) ? Wr1 : (l == 1) ? Wr2 : Wr3;
    const float* src = (j < 256) ? (Wl + (size_t)j * H) : (Wr + (size_t)(j - 256) * H);
    float4 v = *(const float4*)(src + q * 4);
    size_t o = (size_t)l * 512 * H + (size_t)j * H + q * 4;
    *(__half2*)(g_bw + o)     = __float22half2_rn(make_float2(v.x, v.y));
    *(__half2*)(g_bw + o + 2) = __float22half2_rn(make_float2(v.z, v.w));
}

// ================= GEMM: y = h @ [Wl;Wr]^T  (K=256, N=512), plain fp16 =================
// BM=128 BN=128 BK=32; 8 warps (4m x 2n); 4 stages, 3 chunks in flight. (R11 config)
#define ASTRIDE 80
#define ST_A 0
#define ST_B 10240
#define STAGE 20480
#define NSTAGE 4
#define GEMM_SMEM (NSTAGE * STAGE)

__global__ __launch_bounds__(256, 2) void gemm_mma_kernel(int in_sel, int layer)
{
    extern __shared__ char smem[];
    const __half* A  = in_sel ? g_f1 : g_f0;
    const __half* Bw = g_bw + (size_t)layer * 512 * H;
    uint32_t sbase = smem_u32(smem);

    int tid = threadIdx.x;
    int lane = tid & 31, wid = tid >> 5;
    int warp_m = wid & 3, warp_n = wid >> 2;
    int bm = blockIdx.x * 128, bn = blockIdx.y * 128;
    int wm = warp_m * 32, wn = warp_n * 64;

    int am0 = tid >> 2, aq = (tid & 3) * 8;
    int am1 = am0 + 64;
    int brow = tid >> 1, bq = (tid & 1) * 2;
    int gm0 = bm + am0, gm1 = bm + am1;
    int v0 = (gm0 < N_NODES) ? 16 : 0;
    int v1 = (gm1 < N_NODES) ? 16 : 0;
    int c0 = (gm0 < N_NODES) ? gm0 : N_NODES - 1;
    int c1 = (gm1 < N_NODES) ? gm1 : N_NODES - 1;

    auto issue = [&](int stage, int c) {
        uint32_t sb = sbase + stage * STAGE;
        int kk = c * 32;
        uint32_t sa0 = sb + ST_A + am0 * ASTRIDE + (tid & 3) * 16;
        uint32_t sa1 = sb + ST_A + am1 * ASTRIDE + (tid & 3) * 16;
        CP_ASYNC16(sa0, A + (size_t)c0 * H + kk + aq, v0);
        CP_ASYNC16(sa1, A + (size_t)c1 * H + kk + aq, v1);
        uint32_t sbb = sb + ST_B + brow * ASTRIDE + bq * 16;
        const __half* bg = Bw + (size_t)(bn + brow) * H + kk + bq * 8;
        CP_ASYNC16(sbb,      bg,     16);
        CP_ASYNC16(sbb + 16, bg + 8, 16);
    };

    float acc[2][8][4];
    #pragma unroll
    for (int a = 0; a < 2; a++)
        #pragma unroll
        for (int b = 0; b < 8; b++)
            #pragma unroll
            for (int cc = 0; cc < 4; cc++) acc[a][b][cc] = 0.f;

    issue(0, 0); CP_COMMIT();
    issue(1, 1); CP_COMMIT();
    issue(2, 2); CP_COMMIT();

    for (int c = 0; c < 8; c++) {
        CP_WAIT2();
        __syncthreads();

        if (c + 3 < 8) issue((c + 3) % NSTAGE, c + 3);
        CP_COMMIT();

        uint32_t sb = sbase + (c % NSTAGE) * STAGE;
        #pragma unroll
        for (int ks = 0; ks < 2; ks++) {
            uint32_t am[2][4], bh[4][4];
            #pragma unroll
            for (int mt = 0; mt < 2; mt++) {
                int row = wm + mt * 16 + (lane & 15);
                int kk = ks * 16 + (lane >> 4) * 8;
                LDSM_X4(am[mt][0], am[mt][1], am[mt][2], am[mt][3],
                        sb + ST_A + row * ASTRIDE + kk * 2);
            }
            #pragma unroll
            for (int p = 0; p < 4; p++) {
                int n = wn + p * 16 + (lane >> 4) * 8 + (lane & 7);
                int kk = ks * 16 + ((lane >> 3) & 1) * 8;
                LDSM_X4(bh[p][0], bh[p][1], bh[p][2], bh[p][3],
                        sb + ST_B + n * ASTRIDE + kk * 2);
            }
            #pragma unroll
            for (int mt = 0; mt < 2; mt++) {
                #pragma unroll
                for (int nt = 0; nt < 8; nt++) {
                    MMA_FP16(acc[mt][nt], am[mt],
                             bh[nt >> 1][(nt & 1) * 2], bh[nt >> 1][(nt & 1) * 2 + 1]);
                }
            }
        }
    }

    // epilogue: cols <256 -> y_l fp16; cols >=256 -> y_r fp16
    int isR = (bn >= 256);
    __half* Yout = isR ? g_yr : g_y;
    int coff = isR ? 256 : 0;
    #pragma unroll
    for (int mt = 0; mt < 2; mt++) {
        #pragma unroll
        for (int nt = 0; nt < 8; nt++) {
            int row0 = bm + wm + mt * 16 + (lane >> 2);
            int row1 = row0 + 8;
            int col  = bn + wn + nt * 8 + (lane & 3) * 2 - coff;
            if (row0 < N_NODES)
                *(__half2*)(Yout + (size_t)row0 * H + col) =
                    __float22half2_rn(make_float2(acc[mt][nt][0], acc[mt][nt][1]));
            if (row1 < N_NODES)
                *(__half2*)(Yout + (size_t)row1 * H + col) =
                    __float22half2_rn(make_float2(acc[mt][nt][2], acc[mt][nt][3]));
        }
    }
}

// ================= combine: mean(y_l) + y_r + bias -> ELU =================
__global__ __launch_bounds__(256) void combine_kernel(
    const float* __restrict__ bias, int out_sel /*0->f0, 1->f1, 2->fp32 out*/,
    float* __restrict__ out_f32)
{
    int node = blockIdx.x * 8 + (threadIdx.x >> 5);
    int lane = threadIdx.x & 31;
    if (node >= N_NODES) return;
    int beg = g_rowptr[node], end = g_rowptr[node + 1];

    float acc[8];
    #pragma unroll
    for (int i = 0; i < 8; i++) acc[i] = 0.f;

    int j = beg;
    for (; j + 2 <= end; j += 2) {
        int s0 = g_col[j], s1 = g_col[j + 1];
        uint4 u0 = __ldg((const uint4*)(g_y + (size_t)s0 * H) + lane);
        uint4 u1 = __ldg((const uint4*)(g_y + (size_t)s1 * H) + lane);
        const __half2* h0 = (const __half2*)&u0;
        const __half2* h1 = (const __half2*)&u1;
        #pragma unroll
        for (int p = 0; p < 4; p++) {
            float2 f0 = __half22float2(h0[p]);
            float2 f1 = __half22float2(h1[p]);
            acc[p * 2 + 0] += f0.x + f1.x;
            acc[p * 2 + 1] += f0.y + f1.y;
        }
    }
    if (j < end) {
        uint4 u0 = __ldg((const uint4*)(g_y + (size_t)g_col[j] * H) + lane);
        const __half2* h0 = (const __half2*)&u0;
        #pragma unroll
        for (int p = 0; p < 4; p++) {
            float2 f0 = __half22float2(h0[p]);
            acc[p * 2 + 0] += f0.x;
            acc[p * 2 + 1] += f0.y;
        }
    }
    float inv = 1.0f / fmaxf((float)(end - beg), 1.0f);

    // y_r fp16: 8 halfs = one uint4
    uint4 ur = __ldg((const uint4*)(g_yr + (size_t)node * H) + lane);
    const __half2* hr = (const __half2*)&ur;
    float rr[8];
    #pragma unroll
    for (int p = 0; p < 4; p++) {
        float2 f = __half22float2(hr[p]);
        rr[p * 2 + 0] = f.x;
        rr[p * 2 + 1] = f.y;
    }
    float4 b0 = __ldg((const float4*)(bias + lane * 8));
    float4 b1 = __ldg((const float4*)(bias + lane * 8 + 4));
    float bb[8] = {b0.x, b0.y, b0.z, b0.w, b1.x, b1.y, b1.z, b1.w};

    float o[8];
    #pragma unroll
    for (int i = 0; i < 8; i++) {
        o[i] = acc[i] * inv + rr[i] + bb[i];
        o[i] = (o[i] > 0.f) ? o[i] : expm1f(o[i]);
    }

    size_t base = (size_t)node * H + lane * 8;
    if (out_sel == 2) {
        *(float4*)(out_f32 + base)     = make_float4(o[0], o[1], o[2], o[3]);
        *(float4*)(out_f32 + base + 4) = make_float4(o[4], o[5], o[6], o[7]);
    } else {
        __half* O = out_sel ? g_f1 : g_f0;
        *(__half2*)(O + base)     = __float22half2_rn(make_float2(o[0], o[1]));
        *(__half2*)(O + base + 2) = __float22half2_rn(make_float2(o[2], o[3]));
        *(__half2*)(O + base + 4) = __float22half2_rn(make_float2(o[4], o[5]));
        *(__half2*)(O + base + 6) = __float22half2_rn(make_float2(o[6], o[7]));
    }
}

// ================= launch =================
extern "C" void kernel_launch(void* const* d_in, const int* in_sizes, int n_in,
                              void* d_out, int out_size) {
    const float* x   = (const float*)d_in[0];
    const void*  ei  = d_in[1];
    const float* Wl1 = (const float*)d_in[2];
    const float* Wr1 = (const float*)d_in[3];
    const float* Wl2 = (const float*)d_in[4];
    const float* Wr2 = (const float*)d_in[5];
    const float* Wl3 = (const float*)d_in[6];
    const float* Wr3 = (const float*)d_in[7];
    const float* bl1 = (const float*)d_in[8];
    const float* bl2 = (const float*)d_in[9];
    const float* bl3 = (const float*)d_in[10];
    float* out = (float*)d_out;

    cudaFuncSetAttribute(gemm_mma_kernel, cudaFuncAttributeMaxDynamicSharedMemorySize, GEMM_SMEM);

    const int SCAN_BLKS = (N_NODES + 255) / 256;
    dim3 ggrid((N_NODES + 127) / 128, 4);
    int cblocks = (N_NODES + 7) / 8;

    cudaStream_t s1;
    cudaStreamCreateWithFlags(&s1, cudaStreamNonBlocking);
    cudaEvent_t eFork, eJoin;
    cudaEventCreateWithFlags(&eFork, cudaEventDisableTiming);
    cudaEventCreateWithFlags(&eJoin, cudaEventDisableTiming);

    // main branch first so gemm1 is the 4th launch (ncu samples #4)
    detect_kernel<<<1, 32>>>((const int*)ei);
    cudaEventRecord(eFork, 0);
    conv_x_kernel<<<(N_NODES * H / 4 + 255) / 256, 256>>>(x);
    conv_w_kernel<<<(3 * 512 * H / 4 + 255) / 256, 256>>>(Wl1, Wr1, Wl2, Wr2, Wl3, Wr3);
    gemm_mma_kernel<<<ggrid, 256, GEMM_SMEM>>>(0, 0);     // layer-1 GEMM (profiled)

    // side branch: CSR build (waits on detect), overlaps conv+gemm1
    cudaStreamWaitEvent(s1, eFork, 0);
    zero_deg_kernel<<<SCAN_BLKS, 256, 0, s1>>>();
    hist_kernel<<<(N_EDGES + 255) / 256, 256, 0, s1>>>(ei);
    scan1_kernel<<<SCAN_BLKS, 256, 0, s1>>>();
    scan2_kernel<<<1, 256, 0, s1>>>(SCAN_BLKS);
    scan3_kernel<<<SCAN_BLKS, 256, 0, s1>>>(SCAN_BLKS);
    fill_kernel<<<(N_EDGES + 255) / 256, 256, 0, s1>>>(ei);
    cudaEventRecord(eJoin, s1);

    cudaStreamWaitEvent(0, eJoin, 0);                     // combine needs CSR

    combine_kernel<<<cblocks, 256>>>(bl1, 1, out);        // layer 1 -> f1
    gemm_mma_kernel<<<ggrid, 256, GEMM_SMEM>>>(1, 1);     // layer 2
    combine_kernel<<<cblocks, 256>>>(bl2, 0, out);        //        -> f0
    gemm_mma_kernel<<<ggrid, 256, GEMM_SMEM>>>(0, 2);     // layer 3
    combine_kernel<<<cblocks, 256>>>(bl3, 2, out);        //        -> d_out
}